// round 1
// baseline (speedup 1.0000x reference)
#include <cuda_runtime.h>
#include <cuda_bf16.h>

#define B_      8
#define NVAL    1024
#define MVAL    1024
#define CIN     8
#define CREP    9
#define COUT    16

#define TM      32          // m-values per block
#define NSPLIT  8           // n-chunks per block
#define NTHREADS (TM * NSPLIT)   // 256
#define NCHUNK  (NVAL / NSPLIT)  // 128

// Fast exp2 for x <= 0, flush-to-~zero below -126. ~10 fixed-latency ops,
// all on the fma/alu pipes (no MUFU). Rel err ~2e-6 on the poly range.
__device__ __forceinline__ float fast_exp2(float x) {
    x = fmaxf(x, -126.0f);
    float t = x + 12582912.0f;                 // 1.5*2^23: round-to-nearest-int trick
    int   i = __float_as_int(t) << 23;         // integer part -> exponent offset
    float f = x - (t - 12582912.0f);           // frac in [-0.5, 0.5]
    float p =            1.3333558e-3f;
    p = fmaf(p, f,       9.6180489e-3f);
    p = fmaf(p, f,       5.5504109e-2f);
    p = fmaf(p, f,       2.4022651e-1f);
    p = fmaf(p, f,       6.9314718e-1f);
    p = fmaf(p, f,       1.0f);
    return __int_as_float(__float_as_int(p) + i);
}

__global__ __launch_bounds__(NTHREADS)
void convcnp_kernel(const float* __restrict__ gx,
                    const float* __restrict__ gy,
                    const float* __restrict__ gt,
                    const float* __restrict__ gsigma,
                    const float* __restrict__ gW,
                    const float* __restrict__ gbias,
                    float* __restrict__ gout)
{
    __shared__ float s_x[NVAL];
    __shared__ float s_y[NVAL * CIN];   // 32KB; reused as reduction buffer after main loop

    const int b       = blockIdx.x / (MVAL / TM);
    const int mt      = blockIdx.x % (MVAL / TM);
    const int tid     = threadIdx.x;
    const int m_local = tid & (TM - 1);
    const int ns      = tid >> 5;       // tid / TM, TM==32
    const int m       = mt * TM + m_local;

    // Per-channel exponent coefficients: kk[c] = -0.5*log2e / scale_c^2
    float kk[CREP];
    bool same = true;
    #pragma unroll
    for (int c = 0; c < CREP; c++) {
        float s = __expf(gsigma[c]);
        kk[c] = -0.5f * 1.4426950408889634f / (s * s);
        if (c > 0 && kk[c] != kk[0]) same = false;
    }
    const float kk0 = kk[0];
    const float sf  = same ? sqrtf(-kk0) : 1.0f;   // pre-scale coords in fast path

    // Stage x (scaled) and y into shared
    for (int i = tid; i < NVAL; i += NTHREADS)
        s_x[i] = gx[b * NVAL + i] * sf;
    {
        const float4* y4 = (const float4*)(gy + b * NVAL * CIN);
        float4* sy4 = (float4*)s_y;
        #pragma unroll
        for (int i = tid; i < NVAL * CIN / 4; i += NTHREADS)
            sy4[i] = y4[i];
    }
    const float tm = gt[b * MVAL + m] * sf;
    __syncthreads();

    float acc[CREP];
    #pragma unroll
    for (int c = 0; c < CREP; c++) acc[c] = 0.0f;

    const int n0 = ns * NCHUNK;

    if (same) {
        // Fast path: one exp shared by all 9 channels; arg = -(sf*(x-t))^2 = kk0*d
        #pragma unroll 4
        for (int n = n0; n < n0 + NCHUNK; n++) {
            float a = s_x[n] - tm;
            float e = fast_exp2(-(a * a));
            const float4 ya = *(const float4*)&s_y[n * CIN];
            const float4 yb = *(const float4*)&s_y[n * CIN + 4];
            acc[0] += e;
            acc[1] = fmaf(e, ya.x, acc[1]);
            acc[2] = fmaf(e, ya.y, acc[2]);
            acc[3] = fmaf(e, ya.z, acc[3]);
            acc[4] = fmaf(e, ya.w, acc[4]);
            acc[5] = fmaf(e, yb.x, acc[5]);
            acc[6] = fmaf(e, yb.y, acc[6]);
            acc[7] = fmaf(e, yb.z, acc[7]);
            acc[8] = fmaf(e, yb.w, acc[8]);
        }
    } else {
        // General path: per-channel exponent
        #pragma unroll 2
        for (int n = n0; n < n0 + NCHUNK; n++) {
            float a = s_x[n] - tm;
            float d = a * a;
            const float4 ya = *(const float4*)&s_y[n * CIN];
            const float4 yb = *(const float4*)&s_y[n * CIN + 4];
            acc[0] += fast_exp2(d * kk[0]);
            acc[1] = fmaf(fast_exp2(d * kk[1]), ya.x, acc[1]);
            acc[2] = fmaf(fast_exp2(d * kk[2]), ya.y, acc[2]);
            acc[3] = fmaf(fast_exp2(d * kk[3]), ya.z, acc[3]);
            acc[4] = fmaf(fast_exp2(d * kk[4]), ya.w, acc[4]);
            acc[5] = fmaf(fast_exp2(d * kk[5]), yb.x, acc[5]);
            acc[6] = fmaf(fast_exp2(d * kk[6]), yb.y, acc[6]);
            acc[7] = fmaf(fast_exp2(d * kk[7]), yb.z, acc[7]);
            acc[8] = fmaf(fast_exp2(d * kk[8]), yb.w, acc[8]);
        }
    }

    // Reduce the NSPLIT partial accumulators per m (reuse s_y)
    __syncthreads();
    float* red = s_y;   // layout [NSPLIT][TM][CREP]
    #pragma unroll
    for (int c = 0; c < CREP; c++)
        red[(ns * TM + m_local) * CREP + c] = acc[c];
    __syncthreads();

    if (tid < TM) {
        float sum[CREP];
        #pragma unroll
        for (int c = 0; c < CREP; c++) sum[c] = 0.0f;
        #pragma unroll
        for (int s = 0; s < NSPLIT; s++) {
            #pragma unroll
            for (int c = 0; c < CREP; c++)
                sum[c] += red[(s * TM + tid) * CREP + c];
        }

        float density = sum[0];
        float inv = 1.0f / (density + 1e-8f);
        float yv[CREP];
        yv[0] = density;
        #pragma unroll
        for (int c = 1; c < CREP; c++) yv[c] = sum[c] * inv;

        const int mout = mt * TM + tid;
        float* orow = gout + ((size_t)b * MVAL + mout) * COUT;
        #pragma unroll
        for (int o = 0; o < COUT; o++) {
            float r = __ldg(&gbias[o]);
            #pragma unroll
            for (int c = 0; c < CREP; c++)
                r = fmaf(__ldg(&gW[o * CREP + c]), yv[c], r);
            orow[o] = r;
        }
    }
}

extern "C" void kernel_launch(void* const* d_in, const int* in_sizes, int n_in,
                              void* d_out, int out_size) {
    const float* x     = (const float*)d_in[0];
    const float* y     = (const float*)d_in[1];
    const float* t     = (const float*)d_in[2];
    const float* sigma = (const float*)d_in[3];
    const float* W     = (const float*)d_in[4];
    const float* bias  = (const float*)d_in[5];
    float* out = (float*)d_out;

    dim3 grid(B_ * (MVAL / TM));   // 256 blocks
    convcnp_kernel<<<grid, NTHREADS>>>(x, y, t, sigma, W, bias, out);
}

// round 2
// speedup vs baseline: 1.1210x; 1.1210x over previous
#include <cuda_runtime.h>
#include <cuda_bf16.h>

#define B_      8
#define NVAL    1024
#define MVAL    1024
#define CIN     8
#define CREP    9
#define COUT    16

#define TM      32                 // m-values per block (lane = m)
#define NSPLIT  16                 // n-chunks per block (warp = chunk)
#define NTHREADS (TM * NSPLIT)     // 512
#define NCHUNK  (NVAL / NSPLIT)    // 64

typedef unsigned long long u64;

__device__ __forceinline__ u64 pack2(float lo, float hi) {
    u64 r; asm("mov.b64 %0, {%1, %2};" : "=l"(r) : "f"(lo), "f"(hi)); return r;
}
__device__ __forceinline__ void unpack2(u64 v, float& lo, float& hi) {
    asm("mov.b64 {%0, %1}, %2;" : "=f"(lo), "=f"(hi) : "l"(v));
}
__device__ __forceinline__ u64 add2(u64 a, u64 b) {
    u64 r; asm("add.rn.f32x2 %0, %1, %2;" : "=l"(r) : "l"(a), "l"(b)); return r;
}
__device__ __forceinline__ u64 mul2(u64 a, u64 b) {
    u64 r; asm("mul.rn.f32x2 %0, %1, %2;" : "=l"(r) : "l"(a), "l"(b)); return r;
}
__device__ __forceinline__ u64 fma2(u64 a, u64 b, u64 c) {
    u64 r; asm("fma.rn.f32x2 %0, %1, %2, %3;" : "=l"(r) : "l"(a), "l"(b), "l"(c)); return r;
}
__device__ __forceinline__ float ex2(float x) {   // MUFU.EX2, ~2^-22 rel err
    float r; asm("ex2.approx.f32 %0, %1;" : "=f"(r) : "f"(x)); return r;
}

__global__ __launch_bounds__(NTHREADS)
void convcnp_kernel(const float* __restrict__ gx,
                    const float* __restrict__ gy,
                    const float* __restrict__ gt,
                    const float* __restrict__ gsigma,
                    const float* __restrict__ gW,
                    const float* __restrict__ gbias,
                    float* __restrict__ gout)
{
    __shared__ float s_x [NVAL];        // sf * x
    __shared__ float s_xn[NVAL];        // -sf * x
    __shared__ float s_y [NVAL * CIN];  // 32KB; reused as reduction buffer

    const int b       = blockIdx.x / (MVAL / TM);
    const int mt      = blockIdx.x % (MVAL / TM);
    const int tid     = threadIdx.x;
    const int m_local = tid & (TM - 1);
    const int ns      = tid >> 5;
    const int m       = mt * TM + m_local;

    // Per-channel exponent coefficients: kk[c] = -0.5*log2e / scale_c^2
    float kk[CREP];
    bool same = true;
    #pragma unroll
    for (int c = 0; c < CREP; c++) {
        float s = __expf(gsigma[c]);
        kk[c] = -0.5f * 1.4426950408889634f / (s * s);
        if (c > 0 && kk[c] != kk[0]) same = false;
    }
    const float sf = same ? sqrtf(-kk[0]) : 1.0f;

    // Stage scaled x, negated scaled x, and y into shared
    for (int i = tid; i < NVAL; i += NTHREADS) {
        float v = gx[b * NVAL + i] * sf;
        s_x [i] =  v;
        s_xn[i] = -v;
    }
    {
        const float4* y4 = (const float4*)(gy + b * NVAL * CIN);
        float4* sy4 = (float4*)s_y;
        #pragma unroll
        for (int i = tid; i < NVAL * CIN / 4; i += NTHREADS)
            sy4[i] = y4[i];
    }
    const float tm  = gt[b * MVAL + m] * sf;
    __syncthreads();

    const int n0 = ns * NCHUNK;
    float sum[CREP];

    if (same) {
        const u64 tt  = pack2( tm,  tm);
        const u64 ntt = pack2(-tm, -tm);
        u64 accd  = 0;                       // packed density (even/odd n)
        u64 a12 = 0, a34 = 0, a56 = 0, a78 = 0;  // packed channel pairs

        #pragma unroll 4
        for (int n = n0; n < n0 + NCHUNK; n += 2) {
            // packed (x_n, x_{n+1})
            u64 x2  = *(const u64*)&s_x [n];
            u64 xn2 = *(const u64*)&s_xn[n];
            u64 a2  = add2(x2,  ntt);        // ( x - t)
            u64 na2 = add2(xn2, tt);         // ( t - x) = -(x - t)
            u64 d2  = mul2(a2, na2);         // -(x - t)^2 (pre-scaled)
            float d0, d1; unpack2(d2, d0, d1);
            float e0 = ex2(d0);
            float e1 = ex2(d1);
            accd = add2(accd, pack2(e0, e1));

            u64 ee0 = pack2(e0, e0);
            {
                ulonglong2 yA = *(const ulonglong2*)&s_y[n * CIN];
                ulonglong2 yB = *(const ulonglong2*)&s_y[n * CIN + 4];
                a12 = fma2(ee0, yA.x, a12);
                a34 = fma2(ee0, yA.y, a34);
                a56 = fma2(ee0, yB.x, a56);
                a78 = fma2(ee0, yB.y, a78);
            }
            u64 ee1 = pack2(e1, e1);
            {
                ulonglong2 yA = *(const ulonglong2*)&s_y[(n + 1) * CIN];
                ulonglong2 yB = *(const ulonglong2*)&s_y[(n + 1) * CIN + 4];
                a12 = fma2(ee1, yA.x, a12);
                a34 = fma2(ee1, yA.y, a34);
                a56 = fma2(ee1, yB.x, a56);
                a78 = fma2(ee1, yB.y, a78);
            }
        }
        float dlo, dhi; unpack2(accd, dlo, dhi);
        sum[0] = dlo + dhi;
        unpack2(a12, sum[1], sum[2]);
        unpack2(a34, sum[3], sum[4]);
        unpack2(a56, sum[5], sum[6]);
        unpack2(a78, sum[7], sum[8]);
    } else {
        // General path: per-channel exponent (scalar)
        #pragma unroll
        for (int c = 0; c < CREP; c++) sum[c] = 0.0f;
        #pragma unroll 2
        for (int n = n0; n < n0 + NCHUNK; n++) {
            float a = s_x[n] - tm;
            float d = a * a;
            const float4 ya = *(const float4*)&s_y[n * CIN];
            const float4 yb = *(const float4*)&s_y[n * CIN + 4];
            sum[0] += ex2(d * kk[0]);
            sum[1] = fmaf(ex2(d * kk[1]), ya.x, sum[1]);
            sum[2] = fmaf(ex2(d * kk[2]), ya.y, sum[2]);
            sum[3] = fmaf(ex2(d * kk[3]), ya.z, sum[3]);
            sum[4] = fmaf(ex2(d * kk[4]), ya.w, sum[4]);
            sum[5] = fmaf(ex2(d * kk[5]), yb.x, sum[5]);
            sum[6] = fmaf(ex2(d * kk[6]), yb.y, sum[6]);
            sum[7] = fmaf(ex2(d * kk[7]), yb.z, sum[7]);
            sum[8] = fmaf(ex2(d * kk[8]), yb.w, sum[8]);
        }
    }

    // Reduce the NSPLIT partial accumulators per m (reuse s_y)
    __syncthreads();
    float* red = s_y;   // layout [NSPLIT][TM][CREP] = 18KB
    #pragma unroll
    for (int c = 0; c < CREP; c++)
        red[(ns * TM + m_local) * CREP + c] = sum[c];
    __syncthreads();

    if (tid < TM) {
        float tot[CREP];
        #pragma unroll
        for (int c = 0; c < CREP; c++) tot[c] = 0.0f;
        #pragma unroll
        for (int s = 0; s < NSPLIT; s++) {
            #pragma unroll
            for (int c = 0; c < CREP; c++)
                tot[c] += red[(s * TM + tid) * CREP + c];
        }

        float density = tot[0];
        float inv = 1.0f / (density + 1e-8f);
        float yv[CREP];
        yv[0] = density;
        #pragma unroll
        for (int c = 1; c < CREP; c++) yv[c] = tot[c] * inv;

        const int mout = mt * TM + tid;
        float* orow = gout + ((size_t)b * MVAL + mout) * COUT;
        #pragma unroll
        for (int o = 0; o < COUT; o++) {
            float r = __ldg(&gbias[o]);
            #pragma unroll
            for (int c = 0; c < CREP; c++)
                r = fmaf(__ldg(&gW[o * CREP + c]), yv[c], r);
            orow[o] = r;
        }
    }
}

extern "C" void kernel_launch(void* const* d_in, const int* in_sizes, int n_in,
                              void* d_out, int out_size) {
    const float* x     = (const float*)d_in[0];
    const float* y     = (const float*)d_in[1];
    const float* t     = (const float*)d_in[2];
    const float* sigma = (const float*)d_in[3];
    const float* W     = (const float*)d_in[4];
    const float* bias  = (const float*)d_in[5];
    float* out = (float*)d_out;

    dim3 grid(B_ * (MVAL / TM));   // 256 blocks x 512 threads
    convcnp_kernel<<<grid, NTHREADS>>>(x, y, t, sigma, W, bias, out);
}